// round 1
// baseline (speedup 1.0000x reference)
#include <cuda_runtime.h>
#include <math.h>

#define NTOT 131072
#define DIN 768
#define DH 128
#define DA 32
#define KSEL 64
#define EQCAP 2048

// ---------------- device scratch (allocation-free) ----------------
__device__ float    g_x[(size_t)NTOT * DH];   // post-activation x rows (64 MB)
__device__ float    g_s[NTOT];                // attention scores
__device__ float    g_zs[KSEL * DH];          // weighted selected rows
__device__ unsigned g_maxkey;                 // max score (sortable-uint encoded)
__device__ float    g_Z;                      // softmax denominator over N
__device__ int      g_topidx[KSEL];           // top-64 row indices, value-desc order

// float <-> monotone sortable uint
__device__ __forceinline__ unsigned f2k(float f) {
    unsigned u = __float_as_uint(f);
    return u ^ ((u & 0x80000000u) ? 0xFFFFFFFFu : 0x80000000u);
}
__device__ __forceinline__ float k2f(unsigned k) {
    unsigned u = (k & 0x80000000u) ? (k ^ 0x80000000u) : ~k;
    return __uint_as_float(u);
}

__global__ void init_kernel() { g_maxkey = 0u; }

// ---------------- kernel 1: x = relu(BN(input@W1+b1)); h = tanh(BN(x@Watt1+batt1));
//                  s = h@Watt2 + batt2;  store x, s; block-max -> atomicMax ----------------
__global__ __launch_bounds__(256) void fused_main(
    const float* __restrict__ input, const float* __restrict__ W1,
    const float* __restrict__ b1, const float* __restrict__ g1, const float* __restrict__ be1,
    const float* __restrict__ Watt1, const float* __restrict__ batt1,
    const float* __restrict__ g2, const float* __restrict__ be2,
    const float* __restrict__ Watt2, const float* __restrict__ batt2)
{
    __shared__ union {
        struct { float As[64][16]; float Bs[16][128]; } a;
        struct { float xs[64][132]; float hs[64][33]; } b;
    } sm;
    __shared__ float warpmax[2];

    const int tid = threadIdx.x;
    const int tx = tid & 31, ty = tid >> 5;
    const int m0 = blockIdx.x * 64;
    const float inv = rsqrtf(1.0f + 1e-5f);

    float acc[8][4];
    #pragma unroll
    for (int i = 0; i < 8; i++)
        #pragma unroll
        for (int j = 0; j < 4; j++) acc[i][j] = 0.f;

    const int lm = tid >> 2, lk = (tid & 3) << 2;   // A-tile loader: row lm, 4 floats at lk
    const int bk = tid >> 4, bn = (tid & 15) << 3;  // B-tile loader: k-row bk, 8 floats at bn
    const float* inp_base = input + (size_t)(m0 + lm) * DIN + lk;

    for (int k0 = 0; k0 < DIN; k0 += 16) {
        *(float4*)&sm.a.As[lm][lk] = *(const float4*)(inp_base + k0);
        const float* wb = W1 + (size_t)(k0 + bk) * DH + bn;
        *(float4*)&sm.a.Bs[bk][bn]     = *(const float4*)(wb);
        *(float4*)&sm.a.Bs[bk][bn + 4] = *(const float4*)(wb + 4);
        __syncthreads();
        #pragma unroll
        for (int kk = 0; kk < 16; kk++) {
            float4 bv = *(float4*)&sm.a.Bs[kk][tx << 2];
            #pragma unroll
            for (int i = 0; i < 8; i++) {
                float av = sm.a.As[ty * 8 + i][kk];
                acc[i][0] += av * bv.x; acc[i][1] += av * bv.y;
                acc[i][2] += av * bv.z; acc[i][3] += av * bv.w;
            }
        }
        __syncthreads();
    }

    // BN + ReLU epilogue; write x to smem + global
    const int n0 = tx << 2;
    float4 bb = *(const float4*)(b1  + n0);
    float4 gg = *(const float4*)(g1  + n0);
    float4 ee = *(const float4*)(be1 + n0);
    float sc[4] = {gg.x * inv, gg.y * inv, gg.z * inv, gg.w * inv};
    float bi[4] = {bb.x, bb.y, bb.z, bb.w};
    float sb[4] = {ee.x, ee.y, ee.z, ee.w};
    #pragma unroll
    for (int i = 0; i < 8; i++) {
        int r = ty * 8 + i;
        float4 v;
        v.x = fmaxf((acc[i][0] + bi[0]) * sc[0] + sb[0], 0.f);
        v.y = fmaxf((acc[i][1] + bi[1]) * sc[1] + sb[1], 0.f);
        v.z = fmaxf((acc[i][2] + bi[2]) * sc[2] + sb[2], 0.f);
        v.w = fmaxf((acc[i][3] + bi[3]) * sc[3] + sb[3], 0.f);
        *(float4*)&sm.b.xs[r][n0] = v;
        *(float4*)(g_x + (size_t)(m0 + r) * DH + n0) = v;
    }
    __syncthreads();

    // h = tanh(BN(x @ Watt1 + batt1)) : thread -> (row r, 8 cols at c0)
    {
        int r = tid >> 2, c0 = (tid & 3) << 3;
        float hacc[8];
        #pragma unroll
        for (int c = 0; c < 8; c++) hacc[c] = 0.f;
        for (int kk = 0; kk < DH; kk++) {
            float xv = sm.b.xs[r][kk];
            float4 w0 = *(const float4*)(Watt1 + kk * DA + c0);
            float4 w1 = *(const float4*)(Watt1 + kk * DA + c0 + 4);
            hacc[0] += xv * w0.x; hacc[1] += xv * w0.y;
            hacc[2] += xv * w0.z; hacc[3] += xv * w0.w;
            hacc[4] += xv * w1.x; hacc[5] += xv * w1.y;
            hacc[6] += xv * w1.z; hacc[7] += xv * w1.w;
        }
        #pragma unroll
        for (int c = 0; c < 8; c++) {
            int n = c0 + c;
            sm.b.hs[r][n] = tanhf((hacc[c] + batt1[n]) * (g2[n] * inv) + be2[n]);
        }
    }
    __syncthreads();

    // s = h @ Watt2 + batt2 ; block max -> atomicMax
    if (tid < 64) {
        float s = batt2[0];
        #pragma unroll
        for (int c = 0; c < DA; c++) s += sm.b.hs[tid][c] * Watt2[c];
        g_s[m0 + tid] = s;
        float m = s;
        #pragma unroll
        for (int off = 16; off; off >>= 1)
            m = fmaxf(m, __shfl_xor_sync(0xffffffffu, m, off));
        if ((tid & 31) == 0) warpmax[tid >> 5] = m;
    }
    __syncthreads();
    if (tid == 0) atomicMax(&g_maxkey, f2k(fmaxf(warpmax[0], warpmax[1])));
}

// ---------------- kernel 2: Z = sum exp(s - smax); exact top-64 (radix select),
//                  ties broken by smallest index; rank-order descending ----------------
__global__ __launch_bounds__(1024) void select_topk()
{
    __shared__ unsigned hist[256];
    __shared__ float zpart[32];
    __shared__ int sh_b, sh_cnt;
    __shared__ unsigned selkey[KSEL];
    __shared__ int selidx[KSEL];
    __shared__ int eqidx[EQCAP];
    __shared__ int sh_cg, sh_ce;

    const int tid = threadIdx.x;
    const float smax = k2f(g_maxkey);

    // pass 0: Z + histogram of top byte
    if (tid < 256) hist[tid] = 0;
    __syncthreads();
    float z = 0.f;
    for (int i = tid; i < NTOT; i += 1024) {
        float v = g_s[i];
        z += expf(v - smax);
        atomicAdd(&hist[f2k(v) >> 24], 1u);
    }
    #pragma unroll
    for (int off = 16; off; off >>= 1) z += __shfl_xor_sync(0xffffffffu, z, off);
    if ((tid & 31) == 0) zpart[tid >> 5] = z;
    __syncthreads();

    int need = KSEL;
    unsigned prefix = 0, mask = 0;
    if (tid == 0) {
        float zz = 0.f;
        for (int i = 0; i < 32; i++) zz += zpart[i];
        g_Z = zz;
        int cum = 0, b = 255;
        for (; b > 0; b--) { if (cum + (int)hist[b] >= need) break; cum += (int)hist[b]; }
        sh_b = b; sh_cnt = cum;
    }
    __syncthreads();
    need -= sh_cnt; prefix |= ((unsigned)sh_b) << 24; mask |= 0xFFu << 24;

    for (int shift = 16; shift >= 0; shift -= 8) {
        __syncthreads();
        if (tid < 256) hist[tid] = 0;
        __syncthreads();
        for (int i = tid; i < NTOT; i += 1024) {
            unsigned k = f2k(g_s[i]);
            if ((k & mask) == prefix) atomicAdd(&hist[(k >> shift) & 255u], 1u);
        }
        __syncthreads();
        if (tid == 0) {
            int cum = 0, b = 255;
            for (; b > 0; b--) { if (cum + (int)hist[b] >= need) break; cum += (int)hist[b]; }
            sh_b = b; sh_cnt = cum;
        }
        __syncthreads();
        need -= sh_cnt; prefix |= ((unsigned)sh_b) << shift; mask |= 0xFFu << shift;
    }
    const unsigned T = prefix;   // exact 64th-largest key
    const int e_need = need;     // number of elements equal to T to take

    if (tid == 0) { sh_cg = 0; sh_ce = 0; }
    __syncthreads();
    for (int i = tid; i < NTOT; i += 1024) {
        unsigned k = f2k(g_s[i]);
        if (k > T) { int p = atomicAdd(&sh_cg, 1); selkey[p] = k; selidx[p] = i; }
        else if (k == T) { int p = atomicAdd(&sh_ce, 1); if (p < EQCAP) eqidx[p] = i; }
    }
    __syncthreads();
    if (tid == 0) {
        int cg = sh_cg, ce = sh_ce;
        if (ce <= EQCAP) {
            for (int j = 0; j < e_need; j++) {           // partial selection: e smallest indices
                int mn = j;
                for (int q = j + 1; q < ce; q++) if (eqidx[q] < eqidx[mn]) mn = q;
                int t = eqidx[j]; eqidx[j] = eqidx[mn]; eqidx[mn] = t;
            }
        } else {                                         // pathological tie fallback
            int cnt = 0;
            for (int i = 0; i < NTOT && cnt < e_need; i++)
                if (f2k(g_s[i]) == T) eqidx[cnt++] = i;
        }
        for (int j = 0; j < e_need; j++) { selkey[cg + j] = T; selidx[cg + j] = eqidx[j]; }
    }
    __syncthreads();
    // rank-order: key desc, index asc (matches stable argsort(-A))
    if (tid < KSEL) {
        unsigned mk = selkey[tid]; int mi = selidx[tid];
        int rank = 0;
        for (int j = 0; j < KSEL; j++)
            rank += (selkey[j] > mk) || (selkey[j] == mk && selidx[j] < mi);
        g_topidx[rank] = mi;
    }
}

// ---------------- kernel 3: tail (zs, zq/zk/zv, attention, Wz, fc) ----------------
__global__ __launch_bounds__(1024) void final_kernel(
    const float* __restrict__ Wq, const float* __restrict__ Wk, const float* __restrict__ Wv,
    const float* __restrict__ Wz, const float* __restrict__ bz,
    const float* __restrict__ Wf, const float* __restrict__ bf,
    float* __restrict__ out)
{
    __shared__ float aA[KSEL], w[KSEL];
    __shared__ int idx[KSEL];
    __shared__ float zq[KSEL][DA + 1], zk[KSEL][DA + 1], zv[KSEL][DA + 1];
    __shared__ float zw[KSEL * DA];
    __shared__ float part[8][DH];
    __shared__ float z1[DH];

    const int tid = threadIdx.x;
    const float smax = k2f(g_maxkey);
    const float Zs = g_Z;

    if (tid < KSEL) {
        int id = g_topidx[tid];
        idx[tid] = id;
        aA[tid] = expf(g_s[id] - smax) / Zs;   // A values of top-64, descending order
    }
    __syncthreads();
    if (tid == 0) {                            // w = softmax(A_top64)
        float m = aA[0];
        for (int i = 1; i < KSEL; i++) m = fmaxf(m, aA[i]);
        float ssum = 0.f;
        for (int i = 0; i < KSEL; i++) { float e = expf(aA[i] - m); w[i] = e; ssum += e; }
        float rs = 1.0f / ssum;
        for (int i = 0; i < KSEL; i++) w[i] *= rs;
    }
    __syncthreads();
    for (int e = tid; e < KSEL * DH; e += 1024) {   // zs = x[top] * w
        int i = e >> 7, j = e & 127;
        g_zs[e] = g_x[(size_t)idx[i] * DH + j] * w[i];
    }
    __syncthreads();
    {   // zq/zk/zv = zs @ {Wq,Wk,Wv} : thread -> (row i, 2 cols at c0)
        int i = tid >> 4, c0 = (tid & 15) << 1;
        float q0 = 0, q1 = 0, k0 = 0, k1 = 0, v0 = 0, v1 = 0;
        for (int kk = 0; kk < DH; kk++) {
            float xv = g_zs[i * DH + kk];
            float2 a = *(const float2*)(Wq + kk * DA + c0);
            float2 b = *(const float2*)(Wk + kk * DA + c0);
            float2 c = *(const float2*)(Wv + kk * DA + c0);
            q0 += xv * a.x; q1 += xv * a.y;
            k0 += xv * b.x; k1 += xv * b.y;
            v0 += xv * c.x; v1 += xv * c.y;
        }
        zq[i][c0] = q0; zq[i][c0 + 1] = q1;
        zk[i][c0] = k0; zk[i][c0 + 1] = k1;
        zv[i][c0] = v0; zv[i][c0 + 1] = v1;
    }
    __syncthreads();
    {   // attention: one warp handles 2 rows; probs kept in registers via shfl
        int lane = tid & 31, wid = tid >> 5;
        #pragma unroll
        for (int rr = 0; rr < 2; rr++) {
            int i = wid * 2 + rr;
            float l0 = 0, l1 = 0;
            #pragma unroll
            for (int c = 0; c < DA; c++) {
                float qv = zq[i][c];
                l0 += qv * zk[lane][c];
                l1 += qv * zk[lane + 32][c];
            }
            float m = fmaxf(l0, l1);
            #pragma unroll
            for (int off = 16; off; off >>= 1)
                m = fmaxf(m, __shfl_xor_sync(0xffffffffu, m, off));
            float p0 = expf(l0 - m), p1 = expf(l1 - m);
            float s = p0 + p1;
            #pragma unroll
            for (int off = 16; off; off >>= 1) s += __shfl_xor_sync(0xffffffffu, s, off);
            float rs = 1.0f / s;
            p0 *= rs; p1 *= rs;
            float acc = 0.f;
            #pragma unroll
            for (int j = 0; j < 32; j++) {
                float pj = __shfl_sync(0xffffffffu, p0, j);
                acc += pj * zv[j][lane];
            }
            #pragma unroll
            for (int j = 0; j < 32; j++) {
                float pj = __shfl_sync(0xffffffffu, p1, j);
                acc += pj * zv[j + 32][lane];
            }
            zw[i * DA + lane] = acc;
        }
    }
    __syncthreads();
    {   // z1 = relu(zw_flat @ Wz + bz) : 8 m-groups x 128 n, then reduce
        int g = tid >> 7, n = tid & 127;
        float acc = 0.f;
        int mbase = g * 256;
        #pragma unroll 8
        for (int m = 0; m < 256; m++)
            acc += zw[mbase + m] * __ldg(Wz + (size_t)(mbase + m) * DH + n);
        part[g][n] = acc;
    }
    __syncthreads();
    if (tid < DH) {
        float t = bz[tid];
        #pragma unroll
        for (int g = 0; g < 8; g++) t += part[g][tid];
        z1[tid] = fmaxf(t, 0.f);
    }
    __syncthreads();
    if (tid == 0) {
        float o = bf[0];
        for (int n = 0; n < DH; n++) o += z1[n] * Wf[n];
        out[0] = o;
    }
}

// ---------------- host launcher ----------------
extern "C" void kernel_launch(void* const* d_in, const int* in_sizes, int n_in,
                              void* d_out, int out_size)
{
    const float* input = (const float*)d_in[0];
    const float* W1    = (const float*)d_in[1];
    const float* b1    = (const float*)d_in[2];
    const float* g1    = (const float*)d_in[3];
    const float* be1   = (const float*)d_in[4];
    const float* Watt1 = (const float*)d_in[5];
    const float* batt1 = (const float*)d_in[6];
    const float* g2    = (const float*)d_in[7];
    const float* be2   = (const float*)d_in[8];
    const float* Watt2 = (const float*)d_in[9];
    const float* batt2 = (const float*)d_in[10];
    const float* Wq    = (const float*)d_in[11];
    const float* Wk    = (const float*)d_in[12];
    const float* Wv    = (const float*)d_in[13];
    const float* Wz    = (const float*)d_in[14];
    const float* bz    = (const float*)d_in[15];
    const float* Wf    = (const float*)d_in[16];
    const float* bf    = (const float*)d_in[17];

    init_kernel<<<1, 1>>>();
    fused_main<<<NTOT / 64, 256>>>(input, W1, b1, g1, be1,
                                   Watt1, batt1, g2, be2, Watt2, batt2);
    select_topk<<<1, 1024>>>();
    final_kernel<<<1, 1024>>>(Wq, Wk, Wv, Wz, bz, Wf, bf, (float*)d_out);
}

// round 4
// speedup vs baseline: 1.3016x; 1.3016x over previous
#include <cuda_runtime.h>
#include <cuda_bf16.h>
#include <mma.h>
#include <math.h>
#include <stdint.h>

using namespace nvcuda;

#define NTOT 131072
#define DIN 768
#define DH 128
#define DA 32
#define KSEL 64
#define EQCAP 2048
#define NCHUNK 12
#define APITCH 72   // bf16 elems per smem row (64 data + 8 pad)

// ---------------- device scratch (allocation-free) ----------------
__device__ float          g_x[(size_t)NTOT * DH];     // post-activation x rows (64 MB)
__device__ float          g_s[NTOT];                  // attention scores
__device__ float          g_Z;                        // softmax denominator
__device__ int            g_topidx[KSEL];             // top-64 indices, value-desc order
__device__ float          g_zs[KSEL * DH];
__device__ float          g_zw[KSEL * DA];
__device__ float          g_part[16 * DH];
__device__ __nv_bfloat16  g_Wthi[DH * DIN];           // W1^T hi  [n][k]
__device__ __nv_bfloat16  g_Wtlo[DH * DIN];           // W1^T lo  [n][k]

// ---------------- smem offsets (bytes, within extern dynamic smem) ----------------
// mainloop: AHI/ALO/BHI/BLO, each 128*APITCH bf16 = 18432 B
#define OFF_AHI 0
#define OFF_ALO 18432
#define OFF_BHI 36864
#define OFF_BLO 55296
// epilogue (reuses mainloop region): XS per-warp 32*72 fp32 = 9216 B (8 warps = 73728)
#define OFF_XS  0
#define OFF_W1S 73728                 // 128*32 fp32 = 16384
#define OFF_HP  90112                 // 128*33 fp32 = 16896
#define SM_BYTES 107008

// float -> monotone sortable uint
__device__ __forceinline__ unsigned f2k(float f) {
    unsigned u = __float_as_uint(f);
    return u ^ ((u & 0x80000000u) ? 0xFFFFFFFFu : 0x80000000u);
}

// pack two floats' bf16 hi parts and bf16 residual lo parts
__device__ __forceinline__ void split2(float x, float y, uint32_t& hi2, uint32_t& lo2) {
    __nv_bfloat16 hx = __float2bfloat16(x), hy = __float2bfloat16(y);
    float rx = x - __bfloat162float(hx), ry = y - __bfloat162float(hy);
    __nv_bfloat16 lx = __float2bfloat16(rx), ly = __float2bfloat16(ry);
    hi2 = (uint32_t)__bfloat16_as_ushort(hx) | ((uint32_t)__bfloat16_as_ushort(hy) << 16);
    lo2 = (uint32_t)__bfloat16_as_ushort(lx) | ((uint32_t)__bfloat16_as_ushort(ly) << 16);
}

// ---------------- kernel 0: W1 -> transposed bf16 hi/lo ----------------
__global__ __launch_bounds__(256) void conv_w1(const float* __restrict__ W1) {
    int n = blockIdx.x;
    for (int k = threadIdx.x; k < DIN; k += 256) {
        float v = W1[(size_t)k * DH + n];
        __nv_bfloat16 h = __float2bfloat16(v);
        g_Wthi[n * DIN + k] = h;
        g_Wtlo[n * DIN + k] = __float2bfloat16(v - __bfloat162float(h));
    }
}

// ---------------- kernel 1: WMMA bf16-split GEMM + BN/ReLU + h + s ----------------
__global__ __launch_bounds__(256, 2) void fused_main_tc(
    const float* __restrict__ input,
    const float* __restrict__ b1, const float* __restrict__ g1, const float* __restrict__ be1,
    const float* __restrict__ Watt1, const float* __restrict__ batt1,
    const float* __restrict__ g2, const float* __restrict__ be2,
    const float* __restrict__ Watt2, const float* __restrict__ batt2)
{
    extern __shared__ char sm[];
    __nv_bfloat16* sAhi = (__nv_bfloat16*)(sm + OFF_AHI);
    __nv_bfloat16* sAlo = (__nv_bfloat16*)(sm + OFF_ALO);
    __nv_bfloat16* sBhi = (__nv_bfloat16*)(sm + OFF_BHI);
    __nv_bfloat16* sBlo = (__nv_bfloat16*)(sm + OFF_BLO);

    const int tid = threadIdx.x;
    const int lane = tid & 31, wid = tid >> 5;
    const int wg = wid >> 2;         // 0/1: N half (cols 0..63 / 64..127)
    const int w4 = wid & 3;          // 0..3: M group (rows of 32)
    const int m0 = blockIdx.x * 128;

    wmma::fragment<wmma::accumulator, 16, 16, 16, float> fc[2][4];
    #pragma unroll
    for (int i = 0; i < 2; i++)
        #pragma unroll
        for (int j = 0; j < 4; j++) wmma::fill_fragment(fc[i][j], 0.0f);

    const int row = tid >> 1;                  // 0..127 (A/B tile row), 2 threads/row
    const int k8  = (tid & 1) << 5;            // 0 or 32: which 32-k half this thread loads? no ->
    // loader mapping: each thread handles 4 (row,k8) slots: t = tid + 256*t4
    // row = t>>3 (0..127), k8 = (t&7)*8  (8 bf16 / 8 floats per slot)
    (void)row; (void)k8;

    for (int c = 0; c < NCHUNK; c++) {
        const int k0 = c * 64;
        // prefetch A (DRAM) into regs before the sync
        float4 a0[4], a1[4];
        #pragma unroll
        for (int t4 = 0; t4 < 4; t4++) {
            int t = tid + 256 * t4;
            int r = t >> 3, kk = (t & 7) << 3;
            const float* ap = input + (size_t)(m0 + r) * DIN + k0 + kk;
            a0[t4] = *(const float4*)ap;
            a1[t4] = *(const float4*)(ap + 4);
        }
        if (c > 0) __syncthreads();            // all warps done with prev smem
        #pragma unroll
        for (int t4 = 0; t4 < 4; t4++) {
            int t = tid + 256 * t4;
            int r = t >> 3, kk = (t & 7) << 3;
            // B (L2-resident bf16) direct copy
            uint4 bh = *(const uint4*)(g_Wthi + r * DIN + k0 + kk);
            uint4 bl = *(const uint4*)(g_Wtlo + r * DIN + k0 + kk);
            *(uint4*)(sBhi + r * APITCH + kk) = bh;
            *(uint4*)(sBlo + r * APITCH + kk) = bl;
            // A split fp32 -> bf16 hi/lo
            uint4 hi, lo;
            split2(a0[t4].x, a0[t4].y, hi.x, lo.x);
            split2(a0[t4].z, a0[t4].w, hi.y, lo.y);
            split2(a1[t4].x, a1[t4].y, hi.z, lo.z);
            split2(a1[t4].z, a1[t4].w, hi.w, lo.w);
            *(uint4*)(sAhi + r * APITCH + kk) = hi;
            *(uint4*)(sAlo + r * APITCH + kk) = lo;
        }
        __syncthreads();

        // 3 passes: Ahi*Bhi, Ahi*Blo, Alo*Bhi
        #pragma unroll
        for (int pass = 0; pass < 3; pass++) {
            const __nv_bfloat16* A = (pass == 2) ? sAlo : sAhi;
            const __nv_bfloat16* B = (pass == 1) ? sBlo : sBhi;
            #pragma unroll
            for (int ks = 0; ks < 4; ks++) {
                wmma::fragment<wmma::matrix_a, 16, 16, 16, __nv_bfloat16, wmma::row_major> fa0, fa1;
                wmma::load_matrix_sync(fa0, A + (w4 * 32 + 0)  * APITCH + ks * 16, APITCH);
                wmma::load_matrix_sync(fa1, A + (w4 * 32 + 16) * APITCH + ks * 16, APITCH);
                #pragma unroll
                for (int nf = 0; nf < 4; nf++) {
                    wmma::fragment<wmma::matrix_b, 16, 16, 16, __nv_bfloat16, wmma::col_major> fb;
                    wmma::load_matrix_sync(fb, B + (wg * 64 + nf * 16) * APITCH + ks * 16, APITCH);
                    wmma::mma_sync(fc[0][nf], fa0, fb, fc[0][nf]);
                    wmma::mma_sync(fc[1][nf], fa1, fb, fc[1][nf]);
                }
            }
        }
    }
    __syncthreads();

    // -------- epilogue --------
    float* xs  = (float*)(sm + OFF_XS) + wid * (32 * 72);    // this warp's 32x64 (pitch 72)
    float* W1s = (float*)(sm + OFF_W1S);
    float* hp  = (float*)(sm + OFF_HP);

    #pragma unroll
    for (int i = 0; i < 2; i++)
        #pragma unroll
        for (int j = 0; j < 4; j++)
            wmma::store_matrix_sync(xs + (i * 16) * 72 + j * 16, fc[i][j], 72, wmma::mem_row_major);

    for (int i = tid; i < DH * DA; i += 256) W1s[i] = Watt1[i];
    __syncthreads();

    const float invn = rsqrtf(1.0f + 1e-5f);

    // phase A: BN + ReLU; write back to xs and coalesced store to g_x
    {
        int hr  = lane >> 4;                 // 0/1
        int cc4 = (lane & 15) << 2;          // 0..60
        int c0  = wg * 64 + cc4;
        float4 b4 = __ldg((const float4*)(b1  + c0));
        float4 g4 = __ldg((const float4*)(g1  + c0));
        float4 e4 = __ldg((const float4*)(be1 + c0));
        float s0 = g4.x * invn, s1 = g4.y * invn, s2 = g4.z * invn, s3 = g4.w * invn;
        #pragma unroll
        for (int it = 0; it < 16; it++) {
            int r = it * 2 + hr;
            float4 a = *(float4*)(xs + r * 72 + cc4);
            float4 v;
            v.x = fmaxf((a.x + b4.x) * s0 + e4.x, 0.f);
            v.y = fmaxf((a.y + b4.y) * s1 + e4.y, 0.f);
            v.z = fmaxf((a.z + b4.z) * s2 + e4.z, 0.f);
            v.w = fmaxf((a.w + b4.w) * s3 + e4.w, 0.f);
            *(float4*)(xs + r * 72 + cc4) = v;
            *(float4*)(g_x + (size_t)(m0 + w4 * 32 + r) * DH + c0) = v;
        }
        __syncwarp();
    }

    // phase B: h partial = x(row, wg-half) @ Watt1 ; lane owns row=lane
    float hacc[32];
    #pragma unroll
    for (int c2 = 0; c2 < 32; c2++) hacc[c2] = 0.f;
    for (int cc = 0; cc < 64; cc++) {
        float xv = xs[lane * 72 + cc];
        const float* wr = W1s + (wg * 64 + cc) * DA;
        #pragma unroll
        for (int q = 0; q < 8; q++) {
            float4 wv = *(const float4*)(wr + q * 4);
            hacc[q*4+0] += xv * wv.x; hacc[q*4+1] += xv * wv.y;
            hacc[q*4+2] += xv * wv.z; hacc[q*4+3] += xv * wv.w;
        }
    }
    const int prow = w4 * 32 + lane;
    if (wg == 1) {
        #pragma unroll
        for (int c2 = 0; c2 < 32; c2++) hp[prow * 33 + c2] = hacc[c2];
    }
    __syncthreads();
    if (wg == 0) {
        float s = __ldg(batt2);
        #pragma unroll
        for (int c2 = 0; c2 < 32; c2++) {
            float hc = hacc[c2] + hp[prow * 33 + c2];
            float hv = tanhf((hc + __ldg(batt1 + c2)) * (__ldg(g2 + c2) * invn) + __ldg(be2 + c2));
            s += hv * __ldg(Watt2 + c2);
        }
        g_s[m0 + prow] = s;
    }
}

// ---------------- kernel 2: Z + exact top-64 radix select ----------------
__global__ __launch_bounds__(1024) void select_topk()
{
    __shared__ unsigned hist[256];
    __shared__ float zp[32];
    __shared__ int sh_b, sh_cnt;
    __shared__ unsigned selkey[KSEL];
    __shared__ int selidx[KSEL];
    __shared__ int eqidx[EQCAP];
    __shared__ int sh_cg, sh_ce;

    const int tid = threadIdx.x;
    int need = KSEL;
    unsigned prefix = 0, mask = 0;
    float z = 0.f;

    for (int shift = 24; shift >= 0; shift -= 8) {
        if (tid < 256) hist[tid] = 0;
        __syncthreads();
        for (int i = tid; i < NTOT; i += 1024) {
            float v = g_s[i];
            unsigned k = f2k(v);
            if (shift == 24) z += expf(v);
            if ((k & mask) == prefix) atomicAdd(&hist[(k >> shift) & 255u], 1u);
        }
        if (shift == 24) {
            #pragma unroll
            for (int off = 16; off; off >>= 1) z += __shfl_xor_sync(0xffffffffu, z, off);
            if ((tid & 31) == 0) zp[tid >> 5] = z;
        }
        __syncthreads();
        if (tid == 0) {
            if (shift == 24) {
                float zz = 0.f;
                for (int i = 0; i < 32; i++) zz += zp[i];
                g_Z = zz;
            }
            int cum = 0, b = 255;
            for (; b > 0; b--) { if (cum + (int)hist[b] >= need) break; cum += (int)hist[b]; }
            sh_b = b; sh_cnt = cum;
        }
        __syncthreads();
        need -= sh_cnt; prefix |= ((unsigned)sh_b) << shift; mask |= 0xFFu << shift;
        __syncthreads();
    }
    const unsigned T = prefix;
    const int e_need = need;

    if (tid == 0) { sh_cg = 0; sh_ce = 0; }
    __syncthreads();
    for (int i = tid; i < NTOT; i += 1024) {
        unsigned k = f2k(g_s[i]);
        if (k > T) { int p = atomicAdd(&sh_cg, 1); selkey[p] = k; selidx[p] = i; }
        else if (k == T) { int p = atomicAdd(&sh_ce, 1); if (p < EQCAP) eqidx[p] = i; }
    }
    __syncthreads();
    if (tid == 0) {
        int cg = sh_cg, ce = sh_ce;
        if (ce <= EQCAP) {
            for (int j = 0; j < e_need; j++) {
                int mn = j;
                for (int q = j + 1; q < ce; q++) if (eqidx[q] < eqidx[mn]) mn = q;
                int t = eqidx[j]; eqidx[j] = eqidx[mn]; eqidx[mn] = t;
            }
        } else {
            int cnt = 0;
            for (int i = 0; i < NTOT && cnt < e_need; i++)
                if (f2k(g_s[i]) == T) eqidx[cnt++] = i;
        }
        for (int j = 0; j < e_need; j++) { selkey[cg + j] = T; selidx[cg + j] = eqidx[j]; }
    }
    __syncthreads();
    if (tid < KSEL) {   // rank: key desc, index asc (stable argsort(-A))
        unsigned mk = selkey[tid]; int mi = selidx[tid];
        int rank = 0;
        for (int j = 0; j < KSEL; j++)
            rank += (selkey[j] > mk) || (selkey[j] == mk && selidx[j] < mi);
        g_topidx[rank] = mi;
    }
}

// ---------------- kernel 3a: zs, zq/zk/zv, attention -> zw ----------------
__global__ __launch_bounds__(1024) void tail_a(
    const float* __restrict__ Wq, const float* __restrict__ Wk, const float* __restrict__ Wv)
{
    __shared__ float aA[KSEL], w[KSEL];
    __shared__ int idx[KSEL];
    __shared__ float zq[KSEL][DA + 1], zk[KSEL][DA + 1], zv[KSEL][DA + 1];

    const int tid = threadIdx.x;
    const float Zs = g_Z;

    if (tid < KSEL) {
        int id = g_topidx[tid];
        idx[tid] = id;
        aA[tid] = expf(g_s[id]) / Zs;
    }
    __syncthreads();
    if (tid == 0) {
        float m = aA[0];
        for (int i = 1; i < KSEL; i++) m = fmaxf(m, aA[i]);
        float ssum = 0.f;
        for (int i = 0; i < KSEL; i++) { float e = expf(aA[i] - m); w[i] = e; ssum += e; }
        float rs = 1.0f / ssum;
        for (int i = 0; i < KSEL; i++) w[i] *= rs;
    }
    __syncthreads();
    for (int e = tid; e < KSEL * DH; e += 1024) {
        int i = e >> 7, j = e & 127;
        g_zs[e] = g_x[(size_t)idx[i] * DH + j] * w[i];
    }
    __syncthreads();
    {
        int i = tid >> 4, c0 = (tid & 15) << 1;
        float q0 = 0, q1 = 0, k0 = 0, k1 = 0, v0 = 0, v1 = 0;
        for (int kk = 0; kk < DH; kk++) {
            float xv = g_zs[i * DH + kk];
            float2 a = *(const float2*)(Wq + kk * DA + c0);
            float2 b = *(const float2*)(Wk + kk * DA + c0);
            float2 c = *(const float2*)(Wv + kk * DA + c0);
            q0 += xv * a.x; q1 += xv * a.y;
            k0 += xv * b.x; k1 += xv * b.y;
            v0 += xv * c.x; v1 += xv * c.y;
        }
        zq[i][c0] = q0; zq[i][c0 + 1] = q1;
        zk[i][c0] = k0; zk[i][c0 + 1] = k1;
        zv[i][c0] = v0; zv[i][c0 + 1] = v1;
    }
    __syncthreads();
    {
        int lane = tid & 31, wd = tid >> 5;
        #pragma unroll
        for (int rr = 0; rr < 2; rr++) {
            int i = wd * 2 + rr;
            float l0 = 0, l1 = 0;
            #pragma unroll
            for (int c = 0; c < DA; c++) {
                float qv = zq[i][c];
                l0 += qv * zk[lane][c];
                l1 += qv * zk[lane + 32][c];
            }
            float m = fmaxf(l0, l1);
            #pragma unroll
            for (int off = 16; off; off >>= 1)
                m = fmaxf(m, __shfl_xor_sync(0xffffffffu, m, off));
            float p0 = expf(l0 - m), p1 = expf(l1 - m);
            float ss = p0 + p1;
            #pragma unroll
            for (int off = 16; off; off >>= 1) ss += __shfl_xor_sync(0xffffffffu, ss, off);
            float rs = 1.0f / ss;
            p0 *= rs; p1 *= rs;
            float acc = 0.f;
            #pragma unroll
            for (int j = 0; j < 32; j++) {
                float pj = __shfl_sync(0xffffffffu, p0, j);
                acc += pj * zv[j][lane];
            }
            #pragma unroll
            for (int j = 0; j < 32; j++) {
                float pj = __shfl_sync(0xffffffffu, p1, j);
                acc += pj * zv[j + 32][lane];
            }
            g_zw[i * DA + lane] = acc;
        }
    }
}

// ---------------- kernel 3b: Wz partials (16 blocks, deterministic) ----------------
__global__ __launch_bounds__(128) void tail_b(const float* __restrict__ Wz)
{
    __shared__ float zws[128];
    const int g = blockIdx.x, n = threadIdx.x;
    const int mb = g * 128;
    zws[n] = g_zw[mb + n];
    __syncthreads();
    float acc = 0.f;
    #pragma unroll 8
    for (int m = 0; m < 128; m++)
        acc += zws[m] * __ldg(Wz + (size_t)(mb + m) * DH + n);
    g_part[g * DH + n] = acc;
}

// ---------------- kernel 3c: reduce + relu + fc ----------------
__global__ __launch_bounds__(128) void tail_c(
    const float* __restrict__ bz, const float* __restrict__ Wf,
    const float* __restrict__ bf, float* __restrict__ out)
{
    __shared__ float red[4];
    const int t = threadIdx.x;
    float a = bz[t];
    #pragma unroll
    for (int g = 0; g < 16; g++) a += g_part[g * DH + t];
    float zv = fmaxf(a, 0.f) * Wf[t];
    #pragma unroll
    for (int off = 16; off; off >>= 1) zv += __shfl_xor_sync(0xffffffffu, zv, off);
    if ((t & 31) == 0) red[t >> 5] = zv;
    __syncthreads();
    if (t == 0) out[0] = red[0] + red[1] + red[2] + red[3] + bf[0];
}

// ---------------- host launcher ----------------
extern "C" void kernel_launch(void* const* d_in, const int* in_sizes, int n_in,
                              void* d_out, int out_size)
{
    const float* input = (const float*)d_in[0];
    const float* W1    = (const float*)d_in[1];
    const float* b1    = (const float*)d_in[2];
    const float* g1    = (const float*)d_in[3];
    const float* be1   = (const float*)d_in[4];
    const float* Watt1 = (const float*)d_in[5];
    const float* batt1 = (const float*)d_in[6];
    const float* g2    = (const float*)d_in[7];
    const float* be2   = (const float*)d_in[8];
    const float* Watt2 = (const float*)d_in[9];
    const float* batt2 = (const float*)d_in[10];
    const float* Wq    = (const float*)d_in[11];
    const float* Wk    = (const float*)d_in[12];
    const float* Wv    = (const float*)d_in[13];
    const float* Wz    = (const float*)d_in[14];
    const float* bz    = (const float*)d_in[15];
    const float* Wf    = (const float*)d_in[16];
    const float* bf    = (const float*)d_in[17];

    cudaFuncSetAttribute(fused_main_tc, cudaFuncAttributeMaxDynamicSharedMemorySize, SM_BYTES);

    conv_w1<<<DH, 256>>>(W1);
    fused_main_tc<<<NTOT / 128, 256, SM_BYTES>>>(input, b1, g1, be1,
                                                 Watt1, batt1, g2, be2, Watt2, batt2);
    select_topk<<<1, 1024>>>();
    tail_a<<<1, 1024>>>(Wq, Wk, Wv);
    tail_b<<<16, 128>>>(Wz);
    tail_c<<<1, 128>>>(bz, Wf, bf, (float*)d_out);
}

// round 6
// speedup vs baseline: 1.6984x; 1.3049x over previous
#include <cuda_runtime.h>
#include <cuda_bf16.h>
#include <mma.h>
#include <math.h>
#include <stdint.h>

using namespace nvcuda;

#define NTOT 131072
#define DIN 768
#define DH 128
#define DA 32
#define KSEL 64
#define KC 32
#define NITER 24
#define LCAP 4096
#define EQCAP 4096

// ---------------- device scratch (allocation-free) ----------------
__device__ float          g_x[(size_t)NTOT * DH];     // post-activation x rows (64 MB)
__device__ float          g_s[NTOT];                  // attention scores
__device__ float          g_Z;                        // softmax denominator
__device__ int            g_topidx[KSEL];             // top-64 indices, value-desc order
__device__ float          g_zw[KSEL * DA];
__device__ float          g_part[16 * DH];
__device__ float          g_dummy[DH];                // L2-prefetch sink
__device__ __nv_bfloat16  g_Wthi[DH * DIN];           // W1^T hi  [n][k]
__device__ __nv_bfloat16  g_Wtlo[DH * DIN];           // W1^T lo  [n][k]

// ---------------- fused kernel smem map (bytes) ----------------
// mainloop: STA (fp32 A stage, 128x36f = 18432), AHI/ALO (128x40 bf16 = 10240 ea),
//           BHI[2], BLO[2] (10240 each)
#define OFF_STA 0
#define OFF_AHI 18432
#define OFF_ALO 28672
#define OFF_BHI 38912
#define OFF_BLO 59392
// epilogue (reuses region): XS 16 warps x (16 x 76 f) = 77824; W1S 16384; HP 128x33 f
#define XPITCH 76
#define OFF_XS  0
#define OFF_W1S 77824
#define OFF_HP  94208
#define SM_BYTES 111104

__device__ __forceinline__ uint32_t smem_u32(const void* p) {
    uint32_t a;
    asm("{ .reg .u64 t; cvta.to.shared.u64 t, %1; cvt.u32.u64 %0, t; }" : "=r"(a) : "l"(p));
    return a;
}
__device__ __forceinline__ void cp16(uint32_t s, const void* g) {
    asm volatile("cp.async.cg.shared.global [%0], [%1], 16;" :: "r"(s), "l"(g));
}
__device__ __forceinline__ void cp_commit() { asm volatile("cp.async.commit_group;" ::: "memory"); }
__device__ __forceinline__ void cp_wait0()  { asm volatile("cp.async.wait_group 0;" ::: "memory"); }

// float -> monotone sortable uint
__device__ __forceinline__ unsigned f2k(float f) {
    unsigned u = __float_as_uint(f);
    return u ^ ((u & 0x80000000u) ? 0xFFFFFFFFu : 0x80000000u);
}
// pack two floats' bf16 hi parts and bf16 residual lo parts
__device__ __forceinline__ void split2(float x, float y, uint32_t& hi2, uint32_t& lo2) {
    __nv_bfloat16 hx = __float2bfloat16(x), hy = __float2bfloat16(y);
    float rx = x - __bfloat162float(hx), ry = y - __bfloat162float(hy);
    __nv_bfloat16 lx = __float2bfloat16(rx), ly = __float2bfloat16(ry);
    hi2 = (uint32_t)__bfloat16_as_ushort(hx) | ((uint32_t)__bfloat16_as_ushort(hy) << 16);
    lo2 = (uint32_t)__bfloat16_as_ushort(lx) | ((uint32_t)__bfloat16_as_ushort(ly) << 16);
}

// ---------------- kernel 0: W1 -> transposed bf16 hi/lo, + L2 prefetch of Wz ----------------
__global__ __launch_bounds__(256) void conv_w1(const float* __restrict__ W1,
                                               const float* __restrict__ Wz) {
    int n = blockIdx.x;
    for (int k = threadIdx.x; k < DIN; k += 256) {
        float v = W1[(size_t)k * DH + n];
        __nv_bfloat16 h = __float2bfloat16(v);
        g_Wthi[n * DIN + k] = h;
        g_Wtlo[n * DIN + k] = __float2bfloat16(v - __bfloat162float(h));
    }
    // touch Wz slice: 2048 rows / 128 blocks = 16 rows per block -> L2 resident for tail_b
    float acc = 0.f;
    const float* wzb = Wz + (size_t)n * 16 * DH;
    for (int i = threadIdx.x; i < 16 * DH; i += 256) acc += wzb[i];
    __shared__ float red[8];
    #pragma unroll
    for (int off = 16; off; off >>= 1) acc += __shfl_xor_sync(0xffffffffu, acc, off);
    if ((threadIdx.x & 31) == 0) red[threadIdx.x >> 5] = acc;
    __syncthreads();
    if (threadIdx.x == 0) {
        float t = 0.f;
        for (int i = 0; i < 8; i++) t += red[i];
        g_dummy[n] = t;
    }
}

// ---------------- kernel 1: WMMA bf16-split GEMM (cp.async pipelined) + BN/ReLU + h + s ----------------
__global__ __launch_bounds__(512) void fused_main_tc(
    const float* __restrict__ input,
    const float* __restrict__ b1, const float* __restrict__ g1, const float* __restrict__ be1,
    const float* __restrict__ Watt1, const float* __restrict__ batt1,
    const float* __restrict__ g2, const float* __restrict__ be2,
    const float* __restrict__ Watt2, const float* __restrict__ batt2)
{
    extern __shared__ char sm[];
    const uint32_t su = smem_u32(sm);
    float*         staf = (float*)(sm + OFF_STA);
    __nv_bfloat16* sAhi = (__nv_bfloat16*)(sm + OFF_AHI);
    __nv_bfloat16* sAlo = (__nv_bfloat16*)(sm + OFF_ALO);

    const int tid = threadIdx.x;
    const int lane = tid & 31, wid = tid >> 5;
    const int wg = wid >> 3;          // 0/1: N half (cols 0..63 / 64..127)
    const int w8 = wid & 7;           // 0..7: M group of 16 rows
    const int m0 = blockIdx.x * 128;

    // loader indices
    const int ar0 = tid >> 3,         akk0 = (tid & 7) << 2;          // A rows 0..63
    const int ar1 = (tid + 512) >> 3, akk1 = ((tid + 512) & 7) << 2;  // A rows 64..127
    const int br = tid >> 2,          bkk = (tid & 3) << 3;           // B rows 0..127

    wmma::fragment<wmma::accumulator, 16, 16, 16, float> fc[4];
    #pragma unroll
    for (int j = 0; j < 4; j++) wmma::fill_fragment(fc[j], 0.0f);

    // prologue: issue chunk 0
    {
        cp16(su + OFF_STA + ar0 * 144 + akk0 * 4, input + (size_t)(m0 + ar0) * DIN + akk0);
        cp16(su + OFF_STA + ar1 * 144 + akk1 * 4, input + (size_t)(m0 + ar1) * DIN + akk1);
        cp16(su + OFF_BHI + br * 80 + bkk * 2, g_Wthi + br * DIN + bkk);
        cp16(su + OFF_BLO + br * 80 + bkk * 2, g_Wtlo + br * DIN + bkk);
        cp_commit();
    }

    const int cr = tid >> 2, cf0 = (tid & 3) << 3;   // convert: 4 threads/row, 8 floats each

    for (int c = 0; c < NITER; c++) {
        cp_wait0();
        __syncthreads();                 // chunk c arrived; prev MMA done
        // convert stage fp32 -> sAhi/sAlo
        {
            float4 u0 = *(float4*)(staf + cr * 36 + cf0);
            float4 u1 = *(float4*)(staf + cr * 36 + cf0 + 4);
            uint4 hi, lo;
            split2(u0.x, u0.y, hi.x, lo.x);
            split2(u0.z, u0.w, hi.y, lo.y);
            split2(u1.x, u1.y, hi.z, lo.z);
            split2(u1.z, u1.w, hi.w, lo.w);
            *(uint4*)(sAhi + cr * 40 + cf0) = hi;
            *(uint4*)(sAlo + cr * 40 + cf0) = lo;
        }
        __syncthreads();                 // sA ready; stage free
        if (c + 1 < NITER) {             // issue chunk c+1 (overlaps MMA below)
            const int k0 = (c + 1) * KC;
            const uint32_t bbuf = ((c + 1) & 1) * 10240u;
            cp16(su + OFF_STA + ar0 * 144 + akk0 * 4, input + (size_t)(m0 + ar0) * DIN + k0 + akk0);
            cp16(su + OFF_STA + ar1 * 144 + akk1 * 4, input + (size_t)(m0 + ar1) * DIN + k0 + akk1);
            cp16(su + OFF_BHI + bbuf + br * 80 + bkk * 2, g_Wthi + br * DIN + k0 + bkk);
            cp16(su + OFF_BLO + bbuf + br * 80 + bkk * 2, g_Wtlo + br * DIN + k0 + bkk);
            cp_commit();
        }
        // MMA chunk c
        const __nv_bfloat16* Bhi = (__nv_bfloat16*)(sm + OFF_BHI + (c & 1) * 10240);
        const __nv_bfloat16* Blo = (__nv_bfloat16*)(sm + OFF_BLO + (c & 1) * 10240);
        #pragma unroll
        for (int ks = 0; ks < 2; ks++) {
            wmma::fragment<wmma::matrix_a, 16, 16, 16, __nv_bfloat16, wmma::row_major> fahi, falo;
            wmma::load_matrix_sync(fahi, sAhi + (w8 * 16) * 40 + ks * 16, 40);
            wmma::load_matrix_sync(falo, sAlo + (w8 * 16) * 40 + ks * 16, 40);
            #pragma unroll
            for (int nf = 0; nf < 4; nf++) {
                wmma::fragment<wmma::matrix_b, 16, 16, 16, __nv_bfloat16, wmma::col_major> fb;
                wmma::load_matrix_sync(fb, Bhi + (wg * 64 + nf * 16) * 40 + ks * 16, 40);
                wmma::mma_sync(fc[nf], fahi, fb, fc[nf]);
                wmma::mma_sync(fc[nf], falo, fb, fc[nf]);
                wmma::load_matrix_sync(fb, Blo + (wg * 64 + nf * 16) * 40 + ks * 16, 40);
                wmma::mma_sync(fc[nf], fahi, fb, fc[nf]);
            }
        }
    }
    __syncthreads();   // all MMA done before smem reuse

    // -------- epilogue --------
    float* xs  = (float*)(sm + OFF_XS) + wid * (16 * XPITCH);
    float* W1s = (float*)(sm + OFF_W1S);
    float* hp  = (float*)(sm + OFF_HP);

    #pragma unroll
    for (int nf = 0; nf < 4; nf++)
        wmma::store_matrix_sync(xs + nf * 16, fc[nf], XPITCH, wmma::mem_row_major);
    for (int i = tid; i < DH * DA; i += 512) W1s[i] = Watt1[i];
    __syncthreads();

    const float invn = rsqrtf(1.0f + 1e-5f);

    // phase A: BN + ReLU; write back to xs + coalesced g_x store
    {
        int hr  = lane >> 4;
        int cc4 = (lane & 15) << 2;
        int c0  = wg * 64 + cc4;
        float4 b4 = __ldg((const float4*)(b1  + c0));
        float4 g4 = __ldg((const float4*)(g1  + c0));
        float4 e4 = __ldg((const float4*)(be1 + c0));
        float s0 = g4.x * invn, s1 = g4.y * invn, s2 = g4.z * invn, s3 = g4.w * invn;
        #pragma unroll
        for (int it = 0; it < 8; it++) {
            int r = it * 2 + hr;
            float4 a = *(float4*)(xs + r * XPITCH + cc4);
            float4 v;
            v.x = fmaxf((a.x + b4.x) * s0 + e4.x, 0.f);
            v.y = fmaxf((a.y + b4.y) * s1 + e4.y, 0.f);
            v.z = fmaxf((a.z + b4.z) * s2 + e4.z, 0.f);
            v.w = fmaxf((a.w + b4.w) * s3 + e4.w, 0.f);
            *(float4*)(xs + r * XPITCH + cc4) = v;
            *(float4*)(g_x + (size_t)(m0 + w8 * 16 + r) * DH + c0) = v;
        }
        __syncwarp();
    }

    // phase B: h partial; lane owns (row rl, out-col half ch)
    const int rl = lane & 15, ch = lane >> 4;
    float hacc[16];
    #pragma unroll
    for (int j = 0; j < 16; j++) hacc[j] = 0.f;
    for (int cc = 0; cc < 64; cc++) {
        float xv = xs[rl * XPITCH + cc];
        const float* wr = W1s + (wg * 64 + cc) * DA + ch * 16;
        #pragma unroll
        for (int q = 0; q < 4; q++) {
            float4 wv = *(const float4*)(wr + q * 4);
            hacc[q*4+0] += xv * wv.x; hacc[q*4+1] += xv * wv.y;
            hacc[q*4+2] += xv * wv.z; hacc[q*4+3] += xv * wv.w;
        }
    }
    const int prow = w8 * 16 + rl;
    if (wg == 1) {
        #pragma unroll
        for (int j = 0; j < 16; j++) hp[prow * 33 + ch * 16 + j] = hacc[j];
    }
    __syncthreads();
    if (wg == 0) {
        float sp = 0.f;
        #pragma unroll
        for (int j = 0; j < 16; j++) {
            int n = ch * 16 + j;
            float hc = hacc[j] + hp[prow * 33 + n];
            float hv = tanhf((hc + __ldg(batt1 + n)) * (__ldg(g2 + n) * invn) + __ldg(be2 + n));
            sp += hv * __ldg(Watt2 + n);
        }
        float st = sp + __shfl_xor_sync(0xffffffffu, sp, 16);
        if (ch == 0) g_s[m0 + prow] = st + __ldg(batt2);
    }
}

// ---------------- kernel 2: Z + exact top-64 (11-bit hist + survivor-list radix refine) ----------------
__global__ __launch_bounds__(1024) void select_topk()
{
    extern __shared__ char sm2[];
    unsigned* hist = (unsigned*)(sm2);                 // 2048 bins (reused as 256/32)
    unsigned* lkey = (unsigned*)(sm2 + 8192);          // LCAP
    int*      lidx = (int*)(sm2 + 8192 + LCAP * 4);    // LCAP
    int*      eqidx = (int*)(sm2 + 8192 + LCAP * 8);   // EQCAP
    __shared__ float zp[32];
    __shared__ int sh_b, sh_cnt, sh_lc, sh_ovf, sh_cg, sh_ce;
    __shared__ unsigned selkey[KSEL];
    __shared__ int selidx[KSEL];

    const int tid = threadIdx.x;
    for (int i = tid; i < 2048; i += 1024) hist[i] = 0;
    if (tid == 0) { sh_lc = 0; sh_ovf = 0; }
    __syncthreads();

    // pass 1: full scan — Z and 11-bit histogram
    float z = 0.f;
    for (int i = tid; i < NTOT; i += 1024) {
        float v = g_s[i];
        z += expf(v);
        atomicAdd(&hist[f2k(v) >> 21], 1u);
    }
    #pragma unroll
    for (int off = 16; off; off >>= 1) z += __shfl_xor_sync(0xffffffffu, z, off);
    if ((tid & 31) == 0) zp[tid >> 5] = z;
    __syncthreads();
    if (tid == 0) {
        float zz = 0.f;
        for (int i = 0; i < 32; i++) zz += zp[i];
        g_Z = zz;
        int cum = 0, b = 2047;
        for (; b > 0; b--) { if (cum + (int)hist[b] >= KSEL) break; cum += (int)hist[b]; }
        sh_b = b; sh_cnt = cum;
    }
    __syncthreads();
    int need = KSEL - sh_cnt;
    const unsigned b1 = (unsigned)sh_b;
    unsigned prefix = b1 << 21, mask = 0xFFE00000u;

    // collect survivors (all keys in bins >= b1)
    for (int i = tid; i < NTOT; i += 1024) {
        unsigned k = f2k(g_s[i]);
        if ((k >> 21) >= b1) {
            int p = atomicAdd(&sh_lc, 1);
            if (p < LCAP) { lkey[p] = k; lidx[p] = i; }
            else sh_ovf = 1;
        }
    }
    __syncthreads();
    const int lc = (sh_lc < LCAP) ? sh_lc : LCAP;
    const bool useList = (sh_ovf == 0);

    // refine remaining 21 bits: (shift,width) = (13,8),(5,8),(0,5)
    #pragma unroll
    for (int p3 = 0; p3 < 3; p3++) {
        const int shift = (p3 == 0) ? 13 : (p3 == 1) ? 5 : 0;
        const unsigned bm = (p3 == 2) ? 31u : 255u;
        __syncthreads();
        if (tid < 256) hist[tid] = 0;
        __syncthreads();
        if (useList) {
            for (int j = tid; j < lc; j += 1024) {
                unsigned k = lkey[j];
                if ((k & mask) == prefix) atomicAdd(&hist[(k >> shift) & bm], 1u);
            }
        } else {
            for (int i = tid; i < NTOT; i += 1024) {
                unsigned k = f2k(g_s[i]);
                if ((k & mask) == prefix) atomicAdd(&hist[(k >> shift) & bm], 1u);
            }
        }
        __syncthreads();
        if (tid == 0) {
            int cum = 0, b = (int)bm;
            for (; b > 0; b--) { if (cum + (int)hist[b] >= need) break; cum += (int)hist[b]; }
            sh_b = b; sh_cnt = cum;
        }
        __syncthreads();
        need -= sh_cnt;
        prefix |= ((unsigned)sh_b) << shift;
        mask |= bm << shift;
    }
    const unsigned T = prefix;
    const int e_need = need;

    if (tid == 0) { sh_cg = 0; sh_ce = 0; }
    __syncthreads();
    if (useList) {
        for (int j = tid; j < lc; j += 1024) {
            unsigned k = lkey[j];
            if (k > T) { int p = atomicAdd(&sh_cg, 1); selkey[p] = k; selidx[p] = lidx[j]; }
            else if (k == T) { int p = atomicAdd(&sh_ce, 1); if (p < EQCAP) eqidx[p] = lidx[j]; }
        }
    } else {
        for (int i = tid; i < NTOT; i += 1024) {
            unsigned k = f2k(g_s[i]);
            if (k > T) { int p = atomicAdd(&sh_cg, 1); selkey[p] = k; selidx[p] = i; }
            else if (k == T) { int p = atomicAdd(&sh_ce, 1); if (p < EQCAP) eqidx[p] = i; }
        }
    }
    __syncthreads();
    if (tid == 0) {
        int cg = sh_cg, ce = sh_ce;
        if (ce <= EQCAP) {
            for (int j = 0; j < e_need; j++) {           // e smallest indices among ties
                int mn = j;
                for (int q = j + 1; q < ce; q++) if (eqidx[q] < eqidx[mn]) mn = q;
                int t = eqidx[j]; eqidx[j] = eqidx[mn]; eqidx[mn] = t;
            }
        } else {                                         // pathological tie fallback
            int cnt = 0;
            for (int i = 0; i < NTOT && cnt < e_need; i++)
                if (f2k(g_s[i]) == T) eqidx[cnt++] = i;
        }
        for (int j = 0; j < e_need; j++) { selkey[cg + j] = T; selidx[cg + j] = eqidx[j]; }
    }
    __syncthreads();
    if (tid < KSEL) {   // rank: key desc, index asc (stable argsort(-A))
        unsigned mk = selkey[tid]; int mi = selidx[tid];
        int rank = 0;
        for (int j = 0; j < KSEL; j++)
            rank += (selkey[j] > mk) || (selkey[j] == mk && selidx[j] < mi);
        g_topidx[rank] = mi;
    }
}

// ---------------- kernel 3a: zs, zq/zk/zv, attention -> zw (all in smem) ----------------
#define TA_ZS   0                        // 64*129 f  = 33024
#define TA_WQ   33024                    // 128*33 f  = 16896
#define TA_WK   49920
#define TA_WV   66816
#define TA_ZQ   83712                    // 64*33 f   = 8448
#define TA_ZK   92160
#define TA_ZV   100608
#define TA_BYTES 109056
__global__ __launch_bounds__(1024) void tail_a(
    const float* __restrict__ Wq, const float* __restrict__ Wk, const float* __restrict__ Wv)
{
    extern __shared__ char sm3[];
    float* zs = (float*)(sm3 + TA_ZS);
    float* wq = (float*)(sm3 + TA_WQ);
    float* wk = (float*)(sm3 + TA_WK);
    float* wv = (float*)(sm3 + TA_WV);
    float* zq = (float*)(sm3 + TA_ZQ);
    float* zk = (float*)(sm3 + TA_ZK);
    float* zv = (float*)(sm3 + TA_ZV);
    __shared__ float aA[KSEL], w[KSEL];
    __shared__ int idx[KSEL];

    const int tid = threadIdx.x;
    const float Zs = g_Z;

    if (tid < KSEL) {
        int id = g_topidx[tid];
        idx[tid] = id;
        aA[tid] = expf(g_s[id]) / Zs;
    }
    for (int i = tid; i < DH * DA; i += 1024) {       // stage Wq/Wk/Wv
        int r = i >> 5, c = i & 31;
        wq[r * 33 + c] = Wq[i];
        wk[r * 33 + c] = Wk[i];
        wv[r * 33 + c] = Wv[i];
    }
    __syncthreads();
    if (tid == 0) {                                   // w = softmax(A_top64)
        float m = aA[0];
        for (int i = 1; i < KSEL; i++) m = fmaxf(m, aA[i]);
        float ssum = 0.f;
        for (int i = 0; i < KSEL; i++) { float e = expf(aA[i] - m); w[i] = e; ssum += e; }
        float rs = 1.0f / ssum;
        for (int i = 0; i < KSEL; i++) w[i] *= rs;
    }
    __syncthreads();
    for (int e = tid; e < KSEL * DH; e += 1024) {     // zs = x[top] * w  (smem)
        int i = e >> 7, j = e & 127;
        zs[i * 129 + j] = g_x[(size_t)idx[i] * DH + j] * w[i];
    }
    __syncthreads();
    {   // zq/zk/zv = zs @ {Wq,Wk,Wv}: thread -> (row i, 2 cols)
        int i = tid >> 4, c0 = (tid & 15) << 1;
        float q0 = 0, q1 = 0, k0 = 0, k1 = 0, v0 = 0, v1 = 0;
        for (int kk = 0; kk < DH; kk++) {
            float xv = zs[i * 129 + kk];
            q0 += xv * wq[kk * 33 + c0]; q1 += xv * wq[kk * 33 + c0 + 1];
            k0 += xv * wk[kk * 33 + c0]; k1 += xv * wk[kk * 33 + c0 + 1];
            v0 += xv * wv[kk * 33 + c0]; v1 += xv * wv[kk * 33 + c0 + 1];
        }
        zq[i * 33 + c0] = q0; zq[i * 33 + c0 + 1] = q1;
        zk[i * 33 + c0] = k0; zk[i * 33 + c0 + 1] = k1;
        zv[i * 33 + c0] = v0; zv[i * 33 + c0 + 1] = v1;
    }
    __syncthreads();
    {   // row attention: one warp -> 2 rows
        int lane = tid & 31, wd = tid >> 5;
        #pragma unroll
        for (int rr = 0; rr < 2; rr++) {
            int i = wd * 2 + rr;
            float l0 = 0, l1 = 0;
            #pragma unroll
            for (int c = 0; c < DA; c++) {
                float qv = zq[i * 33 + c];
                l0 += qv * zk[lane * 33 + c];
                l1 += qv * zk[(lane + 32) * 33 + c];
            }
            float m = fmaxf(l0, l1);
            #pragma unroll
            for (int off = 16; off; off >>= 1)
                m = fmaxf(m, __shfl_xor_sync(0xffffffffu, m, off));
            float p0 = expf(l0 - m), p1 = expf(l1 - m);
            float ss = p0 + p1;
            #pragma unroll
            for (int off = 16; off; off >>= 1) ss += __shfl_xor_sync(0xffffffffu, ss, off);
            float rs = 1.0f / ss;
            p0 *= rs; p1 *= rs;
            float acc = 0.f;
            #pragma unroll
            for (int j = 0; j < 32; j++) {
                float pj = __shfl_sync(0xffffffffu, p0, j);
                acc += pj * zv[j * 33 + lane];
            }
            #pragma unroll
            for (int j = 0; j < 32; j++) {
                float pj = __shfl_sync(0xffffffffu, p1, j);
                acc += pj * zv[(j + 32) * 33 + lane];
            }
            g_zw[i * DA + lane] = acc;
        }
    }
}

// ---------------- kernel 3b: Wz partials (16 blocks, L2-resident Wz) ----------------
__global__ __launch_bounds__(128) void tail_b(const float* __restrict__ Wz)
{
    __shared__ float zws[128];
    const int g = blockIdx.x, n = threadIdx.x;
    const int mb = g * 128;
    zws[n] = g_zw[mb + n];
    __syncthreads();
    float acc = 0.f;
    #pragma unroll 8
    for (int m = 0; m < 128; m++)
        acc += zws[m] * __ldg(Wz + (size_t)(mb + m) * DH + n);
    g_part[g * DH + n] = acc;
}

// ---------------- kernel 3c: reduce + relu + fc ----------------
__global__ __launch_bounds__(128) void tail_c(
    const float* __restrict__ bz, const float* __restrict__ Wf,
    const float* __restrict__ bf, float* __restrict__ out)
{
    __shared__ float red[4];
    const int t = threadIdx.x;
    float a = bz[t];
    #pragma unroll
    for (int g = 0; g < 16; g++) a += g_part[g * DH + t];
    float zv = fmaxf(a, 0.f) * Wf[t];
    #pragma unroll
    for (int off = 16; off; off >>= 1) zv += __shfl_xor_sync(0xffffffffu, zv, off);
    if ((t & 31) == 0) red[t >> 5] = zv;
    __syncthreads();
    if (t == 0) out[0] = red[0] + red[1] + red[2] + red[3] + bf[0];
}

// ---------------- host launcher ----------------
extern "C" void kernel_launch(void* const* d_in, const int* in_sizes, int n_in,
                              void* d_out, int out_size)
{
    const float* input = (const float*)d_in[0];
    const float* W1    = (const float*)d_in[1];
    const float* b1    = (const float*)d_in[2];
    const float* g1    = (const float*)d_in[3];
    const float* be1   = (const float*)d_in[4];
    const float* Watt1 = (const float*)d_in[5];
    const float* batt1 = (const float*)d_in[6];
    const float* g2    = (const float*)d_in[7];
    const float* be2   = (const float*)d_in[8];
    const float* Watt2 = (const float*)d_in[9];
    const float* batt2 = (const float*)d_in[10];
    const float* Wq    = (const float*)d_in[11];
    const float* Wk    = (const float*)d_in[12];
    const float* Wv    = (const float*)d_in[13];
    const float* Wz    = (const float*)d_in[14];
    const float* bz    = (const float*)d_in[15];
    const float* Wf    = (const float*)d_in[16];
    const float* bf    = (const float*)d_in[17];

    static const int SEL_BYTES = 8192 + LCAP * 8 + EQCAP * 4;
    cudaFuncSetAttribute(fused_main_tc, cudaFuncAttributeMaxDynamicSharedMemorySize, SM_BYTES);
    cudaFuncSetAttribute(select_topk,  cudaFuncAttributeMaxDynamicSharedMemorySize, SEL_BYTES);
    cudaFuncSetAttribute(tail_a,       cudaFuncAttributeMaxDynamicSharedMemorySize, TA_BYTES);

    conv_w1<<<DH, 256>>>(W1, Wz);
    fused_main_tc<<<NTOT / 128, 512, SM_BYTES>>>(input, b1, g1, be1,
                                                 Watt1, batt1, g2, be2, Watt2, batt2);
    select_topk<<<1, 1024, SEL_BYTES>>>();
    tail_a<<<1, 1024, TA_BYTES>>>(Wq, Wk, Wv);
    tail_b<<<16, 128>>>(Wz);
    tail_c<<<1, 128>>>(bz, Wf, bf, (float*)d_out);
}